// round 7
// baseline (speedup 1.0000x reference)
#include <cuda_runtime.h>
#include <cuda_fp16.h>
#include <math.h>
#include <stdint.h>

#define N_NODES  50000
#define N_EDGES  800000
#define N_GRAPHS 256
#define F        128
#define NB       256   // scan blocks
#define CH       196   // nodes per scan block (256*196 >= 50000)

// ---------------- scratch (static __device__ — no allocation anywhere) ----------------
__device__ __half g_h0[N_NODES * F];
__device__ __half g_h1[N_NODES * F];
__device__ float  g_dinv[N_NODES];
__device__ int    g_deg[N_NODES];
__device__ int    g_colptr[N_NODES + 1];
__device__ int    g_cursor[N_NODES];
__device__ int    g_csr[N_EDGES];
__device__ int    g_part[NB];
__device__ int    g_poff[NB];
__device__ int    g_counti[N_GRAPHS];
__device__ int    g_gstart[N_GRAPHS + 1];
__device__ float  g_concat[N_GRAPHS * 192];
__device__ float  g_pool[N_GRAPHS * F];
__device__ float  g_s0[N_GRAPHS * 256];
__device__ float  g_s1[N_GRAPHS * 256];

__device__ __forceinline__ __half* hsel(int s) { return s == 0 ? g_h0 : g_h1; }
__device__ __forceinline__ float* fsel(int s) {
    switch (s) { case 2: return g_concat; case 3: return g_s0; case 5: return g_pool; default: return g_s1; }
}

// ---------------- init ----------------
__global__ void init_kernel() {
    int i = blockIdx.x * blockDim.x + threadIdx.x;
    if (i < N_NODES)  g_deg[i] = 0;
    if (i < N_GRAPHS) g_counti[i] = 0;
}

// ---------------- degree histogram + per-graph counts (fused) ----------------
__global__ void degcnt_kernel(const int* __restrict__ col, const int* __restrict__ batch) {
    int e = blockIdx.x * blockDim.x + threadIdx.x;
    if (e < N_EDGES) atomicAdd(&g_deg[col[e]], 1);
    if (e < N_NODES) atomicAdd(&g_counti[batch[e]], 1);
}

// ---------------- 3-phase parallel scan of degrees -> colptr/cursor (+dinv) -------------
__global__ void scanA_kernel() {
    __shared__ int s[256];
    int t = threadIdx.x, b = blockIdx.x;
    int i = b * CH + t;
    int v = (t < CH && i < N_NODES) ? g_deg[i] : 0;
    s[t] = v;
    __syncthreads();
    for (int off = 128; off > 0; off >>= 1) {
        if (t < off) s[t] += s[t + off];
        __syncthreads();
    }
    if (t == 0) g_part[b] = s[0];
}
__global__ void scanB_kernel() {
    __shared__ int s[NB];
    int t = threadIdx.x;
    int mine = g_part[t];
    s[t] = mine;
    __syncthreads();
    for (int off = 1; off < NB; off <<= 1) {
        int v = (t >= off) ? s[t - off] : 0;
        __syncthreads();
        s[t] += v;
        __syncthreads();
    }
    g_poff[t] = s[t] - mine;
    if (t == 0) g_colptr[N_NODES] = N_EDGES;
}
__global__ void scanC_kernel() {
    __shared__ int s[256];
    int t = threadIdx.x, b = blockIdx.x;
    int i = b * CH + t;
    int d = (t < CH && i < N_NODES) ? g_deg[i] : 0;
    s[t] = d;
    __syncthreads();
    for (int off = 1; off < 256; off <<= 1) {
        int v = (t >= off) ? s[t - off] : 0;
        __syncthreads();
        s[t] += v;
        __syncthreads();
    }
    if (t < CH && i < N_NODES) {
        int cp = g_poff[b] + s[t] - d;
        g_colptr[i] = cp;
        g_cursor[i] = cp;
        g_dinv[i]   = rsqrtf((float)d + 1.0f);
    }
}

// ---------------- CSR fill ----------------
__global__ void csr_fill_kernel(const int* __restrict__ row,
                                const int* __restrict__ col) {
    int e = blockIdx.x * blockDim.x + threadIdx.x;
    if (e < N_EDGES) {
        int c = col[e];
        int pos = atomicAdd(&g_cursor[c], 1);
        g_csr[pos] = row[e];
    }
}

// ---------------- graph boundaries ----------------
__global__ void gstart_kernel() {
    __shared__ int s[N_GRAPHS];
    int t = threadIdx.x;
    s[t] = g_counti[t];
    __syncthreads();
    for (int off = 1; off < N_GRAPHS; off <<= 1) {
        int v = (t >= off) ? s[t - off] : 0;
        __syncthreads();
        s[t] += v;
        __syncthreads();
    }
    g_gstart[t + 1] = s[t];
    if (t == 0) g_gstart[0] = 0;
}

// ---------------- fp16 MMA helper ----------------
__device__ __forceinline__ void mma_f16(float (&c)[4], const uint32_t (&a)[4],
                                        uint32_t b0, uint32_t b1) {
    asm("mma.sync.aligned.m16n8k16.row.col.f32.f16.f16.f32 "
        "{%0,%1,%2,%3},{%4,%5,%6,%7},{%8,%9},{%0,%1,%2,%3};"
        : "+f"(c[0]), "+f"(c[1]), "+f"(c[2]), "+f"(c[3])
        : "r"(a[0]), "r"(a[1]), "r"(a[2]), "r"(a[3]), "r"(b0), "r"(b1));
}

// ---------------- shared agg helpers ----------------
__device__ __forceinline__ void acc_row(float (&a)[8], uint4 v, float sc) {
    float2 p;
    p = __half22float2(*(__half2*)&v.x); a[0] += p.x * sc; a[1] += p.y * sc;
    p = __half22float2(*(__half2*)&v.y); a[2] += p.x * sc; a[3] += p.y * sc;
    p = __half22float2(*(__half2*)&v.z); a[4] += p.x * sc; a[5] += p.y * sc;
    p = __half22float2(*(__half2*)&v.w); a[6] += p.x * sc; a[7] += p.y * sc;
}

// gather+aggregate node i: returns (half==0) packed relu'd result as uint4; acc in fp32.
// out = relu(dinv_i * (sum_j g[j]*dinv_j + g[i]*dinv_i) + bias)
__device__ __forceinline__ uint4 agg_node(const uint4* g4, int i, int half, int li,
                                          const float* bias) {
    int s = g_colptr[i], e = g_colptr[i + 1];
    float di = g_dinv[i];
    float acc[8];
#pragma unroll
    for (int k = 0; k < 8; k++) acc[k] = 0.f;
    if (half == 0) {
        uint4 v = g4[i * 16 + li];
        acc_row(acc, v, di);
    }
    int t = s + half;
    for (; t + 6 < e; t += 8) {     // 4 rows in flight per half-warp
        int j0 = g_csr[t], j1 = g_csr[t + 2], j2 = g_csr[t + 4], j3 = g_csr[t + 6];
        float d0 = g_dinv[j0], d1 = g_dinv[j1], d2 = g_dinv[j2], d3 = g_dinv[j3];
        uint4 v0 = g4[j0 * 16 + li];
        uint4 v1 = g4[j1 * 16 + li];
        uint4 v2 = g4[j2 * 16 + li];
        uint4 v3 = g4[j3 * 16 + li];
        acc_row(acc, v0, d0);
        acc_row(acc, v1, d1);
        acc_row(acc, v2, d2);
        acc_row(acc, v3, d3);
    }
    for (; t < e; t += 2) {
        int j = g_csr[t];
        float dj = g_dinv[j];
        uint4 v = g4[j * 16 + li];
        acc_row(acc, v, dj);
    }
#pragma unroll
    for (int k = 0; k < 8; k++)
        acc[k] += __shfl_down_sync(0xffffffffu, acc[k], 16);
    uint4 ov = make_uint4(0, 0, 0, 0);
    if (half == 0) {
        float4 b0 = *(const float4*)&bias[li * 8];
        float4 b1 = *(const float4*)&bias[li * 8 + 4];
        float r[8];
        r[0] = fmaxf(acc[0] * di + b0.x, 0.f);
        r[1] = fmaxf(acc[1] * di + b0.y, 0.f);
        r[2] = fmaxf(acc[2] * di + b0.z, 0.f);
        r[3] = fmaxf(acc[3] * di + b0.w, 0.f);
        r[4] = fmaxf(acc[4] * di + b1.x, 0.f);
        r[5] = fmaxf(acc[5] * di + b1.y, 0.f);
        r[6] = fmaxf(acc[6] * di + b1.z, 0.f);
        r[7] = fmaxf(acc[7] * di + b1.w, 0.f);
        __half2 h0 = __floats2half2_rn(r[0], r[1]);
        __half2 h1 = __floats2half2_rn(r[2], r[3]);
        __half2 h2 = __floats2half2_rn(r[4], r[5]);
        __half2 h3 = __floats2half2_rn(r[6], r[7]);
        ov.x = *(uint32_t*)&h0; ov.y = *(uint32_t*)&h1;
        ov.z = *(uint32_t*)&h2; ov.w = *(uint32_t*)&h3;
    }
    return ov;
}

// ---------------- fused agg + GEMM: C = relu(agg(g)+b) @ W^T  (half in/out) -------------
// block: 128 nodes, 8 warps; agg fills As smem tile, then MMA (4Mx2N warps, 32x64 tiles).
#define HS 136
#define GEMM_SMEM (2 * 128 * HS * 2)
__global__ __launch_bounds__(256)
void agg_gemm(int srcSel, int dstSel, const float* __restrict__ bias,
              const float* __restrict__ W, int M) {
    extern __shared__ __half sh[];
    __half* As = sh;              // [128][HS]
    __half* Ws = sh + 128 * HS;   // [128][HS]
    const uint4* g4 = (const uint4*)hsel(srcSel);
    __half* C = hsel(dstSel);

    int tid = threadIdx.x;
    int wid = tid >> 5, lane = tid & 31;
    int half = lane >> 4, li = lane & 15;
    int group = lane >> 2, tig = lane & 3;
    int warpM = wid & 3, warpN = wid >> 2;
    int m0 = blockIdx.x * 128;

    // load W -> Ws (fp32 -> half); no sync needed until MMA phase
#pragma unroll
    for (int i = 0; i < 16; i++) {
        int lin = i * 256 + tid;
        int n = lin >> 5, c = (lin & 31) * 4;
        float4 v = *(const float4*)&W[n * 128 + c];
        __half2 h0 = __floats2half2_rn(v.x, v.y);
        __half2 h1 = __floats2half2_rn(v.z, v.w);
        uint2 t;
        t.x = *(uint32_t*)&h0; t.y = *(uint32_t*)&h1;
        *(uint2*)&Ws[n * HS + c] = t;
    }

    // agg phase: warp wid handles nodes m0 + wid*16 .. +15
    for (int nn = 0; nn < 16; nn++) {
        int local = wid * 16 + nn;
        int i = m0 + local;
        if (i < M) {
            uint4 ov = agg_node(g4, i, half, li, bias);
            if (half == 0) *(uint4*)&As[local * HS + li * 8] = ov;
        }
    }
    __syncthreads();

    // MMA phase
    float acc[2][8][4];
#pragma unroll
    for (int mt = 0; mt < 2; mt++)
#pragma unroll
        for (int nt = 0; nt < 8; nt++)
#pragma unroll
            for (int i = 0; i < 4; i++) acc[mt][nt][i] = 0.f;

#pragma unroll
    for (int ks = 0; ks < 8; ks++) {
        int k0 = ks * 16;
        uint32_t a[2][4];
#pragma unroll
        for (int mt = 0; mt < 2; mt++) {
            int r = warpM * 32 + mt * 16 + group;
            a[mt][0] = *(uint32_t*)&As[r * HS + k0 + 2 * tig];
            a[mt][1] = *(uint32_t*)&As[(r + 8) * HS + k0 + 2 * tig];
            a[mt][2] = *(uint32_t*)&As[r * HS + k0 + 8 + 2 * tig];
            a[mt][3] = *(uint32_t*)&As[(r + 8) * HS + k0 + 8 + 2 * tig];
        }
#pragma unroll
        for (int nt = 0; nt < 8; nt++) {
            int n = warpN * 64 + nt * 8 + group;
            uint32_t b0 = *(uint32_t*)&Ws[n * HS + k0 + 2 * tig];
            uint32_t b1 = *(uint32_t*)&Ws[n * HS + k0 + 8 + 2 * tig];
            mma_f16(acc[0][nt], a[0], b0, b1);
            mma_f16(acc[1][nt], a[1], b0, b1);
        }
    }
#pragma unroll
    for (int mt = 0; mt < 2; mt++) {
#pragma unroll
        for (int hh = 0; hh < 2; hh++) {
            int m = m0 + warpM * 32 + mt * 16 + group + hh * 8;
            if (m < M) {
#pragma unroll
                for (int nt = 0; nt < 8; nt++) {
                    int n = warpN * 64 + nt * 8 + tig * 2;
                    __half2 hv = __floats2half2_rn(acc[mt][nt][hh * 2 + 0],
                                                   acc[mt][nt][hh * 2 + 1]);
                    *(uint32_t*)&C[m * 128 + n] = *(uint32_t*)&hv;
                }
            }
        }
    }
}

// ---------------- fp16 tensor-core GEMM (layer 1 only): C = A @ W^T -------------
__global__ __launch_bounds__(256)
void gemm_f16(const float* __restrict__ Aext, const float* __restrict__ W,
              int cSel, int M) {
    extern __shared__ __half sh[];
    __half* As = sh;
    __half* Ws = sh + 128 * HS;
    __half* C = hsel(cSel);

    int tid = threadIdx.x;
    int wid = tid >> 5, lane = tid & 31;
    int group = lane >> 2, tig = lane & 3;
    int warpM = wid & 3, warpN = wid >> 2;
    int m0 = blockIdx.x * 128;

#pragma unroll
    for (int i = 0; i < 8; i++) {
        int lin = i * 256 + tid;
        int r = lin >> 4, c = (lin & 15) * 8;
        float4 v0 = make_float4(0.f, 0.f, 0.f, 0.f), v1 = v0;
        if (m0 + r < M) {
            v0 = *(const float4*)&Aext[(m0 + r) * 128 + c];
            v1 = *(const float4*)&Aext[(m0 + r) * 128 + c + 4];
        }
        __half2 h0 = __floats2half2_rn(v0.x, v0.y);
        __half2 h1 = __floats2half2_rn(v0.z, v0.w);
        __half2 h2 = __floats2half2_rn(v1.x, v1.y);
        __half2 h3 = __floats2half2_rn(v1.z, v1.w);
        uint4 t;
        t.x = *(uint32_t*)&h0; t.y = *(uint32_t*)&h1;
        t.z = *(uint32_t*)&h2; t.w = *(uint32_t*)&h3;
        *(uint4*)&As[r * HS + c] = t;
    }
#pragma unroll
    for (int i = 0; i < 16; i++) {
        int lin = i * 256 + tid;
        int n = lin >> 5, c = (lin & 31) * 4;
        float4 v = *(const float4*)&W[n * 128 + c];
        __half2 h0 = __floats2half2_rn(v.x, v.y);
        __half2 h1 = __floats2half2_rn(v.z, v.w);
        uint2 t;
        t.x = *(uint32_t*)&h0; t.y = *(uint32_t*)&h1;
        *(uint2*)&Ws[n * HS + c] = t;
    }
    __syncthreads();

    float acc[2][8][4];
#pragma unroll
    for (int mt = 0; mt < 2; mt++)
#pragma unroll
        for (int nt = 0; nt < 8; nt++)
#pragma unroll
            for (int i = 0; i < 4; i++) acc[mt][nt][i] = 0.f;

#pragma unroll
    for (int ks = 0; ks < 8; ks++) {
        int k0 = ks * 16;
        uint32_t a[2][4];
#pragma unroll
        for (int mt = 0; mt < 2; mt++) {
            int r = warpM * 32 + mt * 16 + group;
            a[mt][0] = *(uint32_t*)&As[r * HS + k0 + 2 * tig];
            a[mt][1] = *(uint32_t*)&As[(r + 8) * HS + k0 + 2 * tig];
            a[mt][2] = *(uint32_t*)&As[r * HS + k0 + 8 + 2 * tig];
            a[mt][3] = *(uint32_t*)&As[(r + 8) * HS + k0 + 8 + 2 * tig];
        }
#pragma unroll
        for (int nt = 0; nt < 8; nt++) {
            int n = warpN * 64 + nt * 8 + group;
            uint32_t b0 = *(uint32_t*)&Ws[n * HS + k0 + 2 * tig];
            uint32_t b1 = *(uint32_t*)&Ws[n * HS + k0 + 8 + 2 * tig];
            mma_f16(acc[0][nt], a[0], b0, b1);
            mma_f16(acc[1][nt], a[1], b0, b1);
        }
    }
#pragma unroll
    for (int mt = 0; mt < 2; mt++) {
#pragma unroll
        for (int hh = 0; hh < 2; hh++) {
            int m = m0 + warpM * 32 + mt * 16 + group + hh * 8;
            if (m < M) {
#pragma unroll
                for (int nt = 0; nt < 8; nt++) {
                    int n = warpN * 64 + nt * 8 + tig * 2;
                    __half2 hv = __floats2half2_rn(acc[mt][nt][hh * 2 + 0],
                                                   acc[mt][nt][hh * 2 + 1]);
                    *(uint32_t*)&C[m * 128 + n] = *(uint32_t*)&hv;
                }
            }
        }
    }
}

// ---------------- standalone agg (layer 3): h1 <- relu-agg(h0) ----------------
__global__ __launch_bounds__(256)
void agg_kernel(int srcSel, int dstSel, const float* __restrict__ bias) {
    const uint4* g4 = (const uint4*)hsel(srcSel);
    __half* out = hsel(dstSel);
    int warp = (blockIdx.x * blockDim.x + threadIdx.x) >> 5;
    int lane = threadIdx.x & 31;
    if (warp >= N_NODES) return;
    int half = lane >> 4, li = lane & 15;
    uint4 ov = agg_node(g4, warp, half, li, bias);
    if (half == 0) ((uint4*)out)[warp * 16 + li] = ov;
}

// ---------------- pooling: one block per graph, fused divide; reads g_h1 ---------------
__global__ void pool_kernel() {
    __shared__ float s[256];
    const __half* h = g_h1;
    int g = blockIdx.x;
    int tid = threadIdx.x;
    int f = tid & 127, hh = tid >> 7;
    int gs = g_gstart[g], ge = g_gstart[g + 1];
    float acc = 0.f;
    for (int n = gs + hh; n < ge; n += 2)
        acc += __half2float(h[n * F + f]);
    s[tid] = acc;
    __syncthreads();
    if (hh == 0) {
        float cnt = (float)(ge - gs);
        float tot = s[tid] + s[tid + 128];
        g_pool[g * F + f] = tot / fmaxf(cnt, 1.0f);
    }
}

// ---------------- generic small GEMM (fp32): C[M,N] = act(A @ W^T + b) ----------------
__global__ __launch_bounds__(256)
void small_gemm(const float* __restrict__ Aext, int aSel, int aOff, int lda,
                const float* __restrict__ W, const float* __restrict__ bias,
                float* __restrict__ Cext, int cSel, int cOff, int ldc,
                int M, int N, int K, int doRelu) {
    const float* A = (Aext ? Aext : fsel(aSel) + aOff);
    float* C = (Cext ? Cext : fsel(cSel) + cOff);

    __shared__ __align__(16) float As[64][33];
    __shared__ __align__(16) float Ws2[32][68];
    int tid = threadIdx.x;
    int tx = tid & 15, ty = tid >> 4;
    int n0 = blockIdx.x * 64, m0 = blockIdx.y * 64;

    float acc[4][4];
#pragma unroll
    for (int i = 0; i < 4; i++)
#pragma unroll
        for (int j = 0; j < 4; j++) acc[i][j] = 0.f;

    for (int kc = 0; kc < K; kc += 32) {
#pragma unroll
        for (int j = 0; j < 8; j++) {
            int lin = j * 256 + tid;
            int m = lin >> 5, k = lin & 31;
            As[m][k] = (m0 + m < M) ? A[(m0 + m) * lda + kc + k] : 0.f;
        }
#pragma unroll
        for (int j = 0; j < 8; j++) {
            int lin = j * 256 + tid;
            int n = lin >> 5, k = lin & 31;
            Ws2[k][n] = (n0 + n < N) ? W[(n0 + n) * K + kc + k] : 0.f;
        }
        __syncthreads();
#pragma unroll
        for (int k = 0; k < 32; k++) {
            float aa[4];
#pragma unroll
            for (int i = 0; i < 4; i++) aa[i] = As[ty * 4 + i][k];
            float4 b = *(const float4*)&Ws2[k][tx * 4];
            float bb[4] = {b.x, b.y, b.z, b.w};
#pragma unroll
            for (int i = 0; i < 4; i++)
#pragma unroll
                for (int j = 0; j < 4; j++) acc[i][j] += aa[i] * bb[j];
        }
        __syncthreads();
    }
#pragma unroll
    for (int i = 0; i < 4; i++) {
        int m = m0 + ty * 4 + i;
        if (m < M) {
#pragma unroll
            for (int j = 0; j < 4; j++) {
                int n = n0 + tx * 4 + j;
                if (n < N) {
                    float v = acc[i][j];
                    if (bias) v += bias[n];
                    if (doRelu) v = fmaxf(v, 0.f);
                    C[m * ldc + n] = v;
                }
            }
        }
    }
}

// ---------------- launch ----------------
extern "C" void kernel_launch(void* const* d_in, const int* in_sizes, int n_in,
                              void* d_out, int out_size) {
    const float* x         = (const float*)d_in[0];
    const int*   ei        = (const int*)d_in[1];
    const int*   batch     = (const int*)d_in[2];
    const float* mol       = (const float*)d_in[3];
    const float* gcn_W     = (const float*)d_in[4];
    const float* gcn_b     = (const float*)d_in[5];
    const float* gcn_out_W = (const float*)d_in[6];
    const float* gcn_out_b = (const float*)d_in[7];
    const float* mlp_W     = (const float*)d_in[8];
    const float* mlp_b     = (const float*)d_in[9];
    const float* mlp_out_W = (const float*)d_in[10];
    const float* mlp_out_b = (const float*)d_in[11];
    const float* pred_W1   = (const float*)d_in[12];
    const float* pred_b1   = (const float*)d_in[13];
    const float* pred_W2   = (const float*)d_in[14];
    const float* pred_b2   = (const float*)d_in[15];
    const float* out_W     = (const float*)d_in[16];
    const float* out_b     = (const float*)d_in[17];
    float* out = (float*)d_out;

    static cudaStream_t sP = 0, sM = 0;
    static cudaEvent_t evRoot = 0, evP = 0, evM = 0;
    if (!sP) {
        cudaStreamCreateWithFlags(&sP, cudaStreamNonBlocking);
        cudaStreamCreateWithFlags(&sM, cudaStreamNonBlocking);
        cudaEventCreateWithFlags(&evRoot, cudaEventDisableTiming);
        cudaEventCreateWithFlags(&evP, cudaEventDisableTiming);
        cudaEventCreateWithFlags(&evM, cudaEventDisableTiming);
        cudaFuncSetAttribute(gemm_f16, cudaFuncAttributeMaxDynamicSharedMemorySize, GEMM_SMEM);
        cudaFuncSetAttribute(agg_gemm, cudaFuncAttributeMaxDynamicSharedMemorySize, GEMM_SMEM);
    }

    const int GB = (N_NODES + 127) / 128;       // 391
    const int AB = (N_NODES * 32 + 255) / 256;  // 6250

    // ---- fork ----
    cudaEventRecord(evRoot, 0);
    cudaStreamWaitEvent(sP, evRoot, 0);
    cudaStreamWaitEvent(sM, evRoot, 0);

    // stream P: graph preprocessing
    init_kernel<<<196, 256, 0, sP>>>();
    degcnt_kernel<<<3125, 256, 0, sP>>>(ei + N_EDGES, batch);
    scanA_kernel<<<NB, 256, 0, sP>>>();
    scanB_kernel<<<1, NB, 0, sP>>>();
    scanC_kernel<<<NB, 256, 0, sP>>>();
    csr_fill_kernel<<<3125, 256, 0, sP>>>(ei, ei + N_EDGES);
    gstart_kernel<<<1, 256, 0, sP>>>();
    cudaEventRecord(evP, sP);

    // stream M: MLP branch -> g_concat[:, 128:192]
    small_gemm<<<dim3(4, 4), 256, 0, sM>>>(mol, -1, 0, 256, mlp_W,         mlp_b,       nullptr, 3, 0, 256, 256, 256, 256, 1);
    small_gemm<<<dim3(4, 4), 256, 0, sM>>>(nullptr, 3, 0, 256, mlp_W + 65536, mlp_b + 256, nullptr, 4, 0, 256, 256, 256, 256, 1);
    small_gemm<<<dim3(1, 4), 256, 0, sM>>>(nullptr, 4, 0, 256, mlp_out_W,  mlp_out_b,   nullptr, 2, 128, 192, 256, 64, 256, 1);
    cudaEventRecord(evM, sM);

    // main stream: g1 = x @ W1^T -> h0
    gemm_f16<<<GB, 256, GEMM_SMEM>>>(x, gcn_W, 0, N_NODES);

    // join preprocessing, then fused GCN chain
    cudaStreamWaitEvent(0, evP, 0);
    agg_gemm<<<GB, 256, GEMM_SMEM>>>(0, 1, gcn_b,       gcn_W + 128 * 128,     N_NODES); // h0->g2 in h1
    agg_gemm<<<GB, 256, GEMM_SMEM>>>(1, 0, gcn_b + 128, gcn_W + 2 * 128 * 128, N_NODES); // h1->g3 in h0
    agg_kernel<<<AB, 256>>>(0, 1, gcn_b + 256);                                          // h0->h3 in h1

    // pool(h3) -> g_pool, then final GCN linear on pooled (commuted): concat[:,0:128]
    pool_kernel<<<N_GRAPHS, 256>>>();
    small_gemm<<<dim3(2, 4), 256>>>(nullptr, 5, 0, 128, gcn_out_W, gcn_out_b, nullptr, 2, 0, 192, N_GRAPHS, 128, 128, 0);

    // join MLP branch, then prediction head
    cudaStreamWaitEvent(0, evM, 0);
    small_gemm<<<dim3(4, 4), 256>>>(nullptr, 2, 0, 192, pred_W1, pred_b1, nullptr, 3, 0, 256, 256, 256, 192, 1);
    small_gemm<<<dim3(4, 4), 256>>>(nullptr, 3, 0, 256, pred_W2, pred_b2, nullptr, 4, 0, 256, 256, 256, 256, 1);
    small_gemm<<<dim3(1, 4), 256>>>(nullptr, 4, 0, 256, out_W,   out_b,   out,     0, 0, 1,   256, 1,   256, 0);
}

// round 8
// speedup vs baseline: 1.2361x; 1.2361x over previous
#include <cuda_runtime.h>
#include <cuda_fp16.h>
#include <math.h>
#include <stdint.h>

#define N_NODES  50000
#define N_EDGES  800000
#define N_GRAPHS 256
#define F        128
#define NB       256   // scan blocks
#define CH       196   // nodes per scan block (256*196 >= 50000)

// ---------------- scratch (static __device__ — no allocation anywhere) ----------------
__device__ __half g_h0[N_NODES * F];
__device__ __half g_h1[N_NODES * F];
__device__ float  g_dinv[N_NODES];
__device__ int    g_deg[N_NODES];
__device__ int    g_colptr[N_NODES + 1];
__device__ int    g_cursor[N_NODES];
__device__ int    g_csr[N_EDGES];
__device__ int    g_part[NB];
__device__ int    g_poff[NB];
__device__ int    g_counti[N_GRAPHS];
__device__ int    g_gstart[N_GRAPHS + 1];
__device__ float  g_concat[N_GRAPHS * 192];
__device__ float  g_pool[N_GRAPHS * F];
__device__ float  g_s0[N_GRAPHS * 256];
__device__ float  g_s1[N_GRAPHS * 256];

__device__ __forceinline__ __half* hsel(int s) { return s == 0 ? g_h0 : g_h1; }
__device__ __forceinline__ float* fsel(int s) {
    switch (s) { case 2: return g_concat; case 3: return g_s0; case 5: return g_pool; default: return g_s1; }
}

// ---------------- init ----------------
__global__ void init_kernel() {
    int i = blockIdx.x * blockDim.x + threadIdx.x;
    if (i < N_NODES)  g_deg[i] = 0;
    if (i < N_GRAPHS) g_counti[i] = 0;
}

// ---------------- degree histogram + per-graph counts (fused) ----------------
__global__ void degcnt_kernel(const int* __restrict__ col, const int* __restrict__ batch) {
    int e = blockIdx.x * blockDim.x + threadIdx.x;
    if (e < N_EDGES) atomicAdd(&g_deg[col[e]], 1);
    if (e < N_NODES) atomicAdd(&g_counti[batch[e]], 1);
}

// ---------------- 3-phase parallel scan of degrees -> colptr/cursor (+dinv) -------------
__global__ void scanA_kernel() {
    __shared__ int s[256];
    int t = threadIdx.x, b = blockIdx.x;
    int i = b * CH + t;
    int v = (t < CH && i < N_NODES) ? g_deg[i] : 0;
    s[t] = v;
    __syncthreads();
    for (int off = 128; off > 0; off >>= 1) {
        if (t < off) s[t] += s[t + off];
        __syncthreads();
    }
    if (t == 0) g_part[b] = s[0];
}
__global__ void scanB_kernel() {
    __shared__ int s[NB];
    int t = threadIdx.x;
    int mine = g_part[t];
    s[t] = mine;
    __syncthreads();
    for (int off = 1; off < NB; off <<= 1) {
        int v = (t >= off) ? s[t - off] : 0;
        __syncthreads();
        s[t] += v;
        __syncthreads();
    }
    g_poff[t] = s[t] - mine;
    if (t == 0) g_colptr[N_NODES] = N_EDGES;
}
__global__ void scanC_kernel() {
    __shared__ int s[256];
    int t = threadIdx.x, b = blockIdx.x;
    int i = b * CH + t;
    int d = (t < CH && i < N_NODES) ? g_deg[i] : 0;
    s[t] = d;
    __syncthreads();
    for (int off = 1; off < 256; off <<= 1) {
        int v = (t >= off) ? s[t - off] : 0;
        __syncthreads();
        s[t] += v;
        __syncthreads();
    }
    if (t < CH && i < N_NODES) {
        int cp = g_poff[b] + s[t] - d;
        g_colptr[i] = cp;
        g_cursor[i] = cp;
        g_dinv[i]   = rsqrtf((float)d + 1.0f);
    }
}

// ---------------- CSR fill ----------------
__global__ void csr_fill_kernel(const int* __restrict__ row,
                                const int* __restrict__ col) {
    int e = blockIdx.x * blockDim.x + threadIdx.x;
    if (e < N_EDGES) {
        int c = col[e];
        int pos = atomicAdd(&g_cursor[c], 1);
        g_csr[pos] = row[e];
    }
}

// ---------------- graph boundaries ----------------
__global__ void gstart_kernel() {
    __shared__ int s[N_GRAPHS];
    int t = threadIdx.x;
    s[t] = g_counti[t];
    __syncthreads();
    for (int off = 1; off < N_GRAPHS; off <<= 1) {
        int v = (t >= off) ? s[t - off] : 0;
        __syncthreads();
        s[t] += v;
        __syncthreads();
    }
    g_gstart[t + 1] = s[t];
    if (t == 0) g_gstart[0] = 0;
}

// ---------------- fp16 MMA helper ----------------
__device__ __forceinline__ void mma_f16(float (&c)[4], const uint32_t (&a)[4],
                                        uint32_t b0, uint32_t b1) {
    asm("mma.sync.aligned.m16n8k16.row.col.f32.f16.f16.f32 "
        "{%0,%1,%2,%3},{%4,%5,%6,%7},{%8,%9},{%0,%1,%2,%3};"
        : "+f"(c[0]), "+f"(c[1]), "+f"(c[2]), "+f"(c[3])
        : "r"(a[0]), "r"(a[1]), "r"(a[2]), "r"(a[3]), "r"(b0), "r"(b1));
}

// ---------------- fp16 tensor-core GEMM: C[M,128] = A[M,128] @ W[128,128]^T -------------
#define HS 136
#define GEMM_SMEM (2 * 128 * HS * 2)
__global__ __launch_bounds__(256)
void gemm_f16(const float* __restrict__ Aext, int aSel,
              const float* __restrict__ W, int cSel, int M) {
    extern __shared__ __half sh[];
    __half* As = sh;              // [128][HS]
    __half* Ws = sh + 128 * HS;   // [128][HS]
    __half* C = hsel(cSel);

    int tid = threadIdx.x;
    int wid = tid >> 5, lane = tid & 31;
    int group = lane >> 2, tig = lane & 3;
    int warpM = wid & 3, warpN = wid >> 2;
    int m0 = blockIdx.x * 128;

    if (Aext) {
#pragma unroll
        for (int i = 0; i < 8; i++) {
            int lin = i * 256 + tid;
            int r = lin >> 4, c = (lin & 15) * 8;
            float4 v0 = make_float4(0.f, 0.f, 0.f, 0.f), v1 = v0;
            if (m0 + r < M) {
                v0 = *(const float4*)&Aext[(m0 + r) * 128 + c];
                v1 = *(const float4*)&Aext[(m0 + r) * 128 + c + 4];
            }
            __half2 h0 = __floats2half2_rn(v0.x, v0.y);
            __half2 h1 = __floats2half2_rn(v0.z, v0.w);
            __half2 h2 = __floats2half2_rn(v1.x, v1.y);
            __half2 h3 = __floats2half2_rn(v1.z, v1.w);
            uint4 t;
            t.x = *(uint32_t*)&h0; t.y = *(uint32_t*)&h1;
            t.z = *(uint32_t*)&h2; t.w = *(uint32_t*)&h3;
            *(uint4*)&As[r * HS + c] = t;
        }
    } else {
        const __half* A = hsel(aSel);
#pragma unroll
        for (int i = 0; i < 8; i++) {
            int lin = i * 256 + tid;
            int r = lin >> 4, c = (lin & 15) * 8;
            uint4 t = make_uint4(0, 0, 0, 0);
            if (m0 + r < M) t = *(const uint4*)&A[(m0 + r) * 128 + c];
            *(uint4*)&As[r * HS + c] = t;
        }
    }
#pragma unroll
    for (int i = 0; i < 16; i++) {
        int lin = i * 256 + tid;
        int n = lin >> 5, c = (lin & 31) * 4;
        float4 v = *(const float4*)&W[n * 128 + c];
        __half2 h0 = __floats2half2_rn(v.x, v.y);
        __half2 h1 = __floats2half2_rn(v.z, v.w);
        uint2 t;
        t.x = *(uint32_t*)&h0; t.y = *(uint32_t*)&h1;
        *(uint2*)&Ws[n * HS + c] = t;
    }
    __syncthreads();

    float acc[2][8][4];
#pragma unroll
    for (int mt = 0; mt < 2; mt++)
#pragma unroll
        for (int nt = 0; nt < 8; nt++)
#pragma unroll
            for (int i = 0; i < 4; i++) acc[mt][nt][i] = 0.f;

#pragma unroll
    for (int ks = 0; ks < 8; ks++) {
        int k0 = ks * 16;
        uint32_t a[2][4];
#pragma unroll
        for (int mt = 0; mt < 2; mt++) {
            int r = warpM * 32 + mt * 16 + group;
            a[mt][0] = *(uint32_t*)&As[r * HS + k0 + 2 * tig];
            a[mt][1] = *(uint32_t*)&As[(r + 8) * HS + k0 + 2 * tig];
            a[mt][2] = *(uint32_t*)&As[r * HS + k0 + 8 + 2 * tig];
            a[mt][3] = *(uint32_t*)&As[(r + 8) * HS + k0 + 8 + 2 * tig];
        }
#pragma unroll
        for (int nt = 0; nt < 8; nt++) {
            int n = warpN * 64 + nt * 8 + group;
            uint32_t b0 = *(uint32_t*)&Ws[n * HS + k0 + 2 * tig];
            uint32_t b1 = *(uint32_t*)&Ws[n * HS + k0 + 8 + 2 * tig];
            mma_f16(acc[0][nt], a[0], b0, b1);
            mma_f16(acc[1][nt], a[1], b0, b1);
        }
    }
#pragma unroll
    for (int mt = 0; mt < 2; mt++) {
#pragma unroll
        for (int hh = 0; hh < 2; hh++) {
            int m = m0 + warpM * 32 + mt * 16 + group + hh * 8;
            if (m < M) {
#pragma unroll
                for (int nt = 0; nt < 8; nt++) {
                    int n = warpN * 64 + nt * 8 + tig * 2;
                    __half2 hv = __floats2half2_rn(acc[mt][nt][hh * 2 + 0],
                                                   acc[mt][nt][hh * 2 + 1]);
                    *(uint32_t*)&C[m * 128 + n] = *(uint32_t*)&hv;
                }
            }
        }
    }
}

// ---------------- CSR aggregation (half, uint4, 4 rows in flight per half-warp) ----------
// out[i] = relu(dinv[i] * (sum_j g[j]*dinv[j] + g[i]*dinv[i]) + b)
__device__ __forceinline__ void acc_row(float (&a)[8], uint4 v, float sc) {
    float2 p;
    p = __half22float2(*(__half2*)&v.x); a[0] += p.x * sc; a[1] += p.y * sc;
    p = __half22float2(*(__half2*)&v.y); a[2] += p.x * sc; a[3] += p.y * sc;
    p = __half22float2(*(__half2*)&v.z); a[4] += p.x * sc; a[5] += p.y * sc;
    p = __half22float2(*(__half2*)&v.w); a[6] += p.x * sc; a[7] += p.y * sc;
}

__global__ __launch_bounds__(256)
void agg_kernel(int srcSel, int dstSel, const float* __restrict__ bias) {
    const uint4* g4 = (const uint4*)hsel(srcSel);
    __half* out = hsel(dstSel);
    int warp = (blockIdx.x * blockDim.x + threadIdx.x) >> 5;
    int lane = threadIdx.x & 31;
    if (warp >= N_NODES) return;
    int i = warp;
    int half = lane >> 4, li = lane & 15;
    int s = g_colptr[i], e = g_colptr[i + 1];

    float di = g_dinv[i];
    float acc[8];
#pragma unroll
    for (int k = 0; k < 8; k++) acc[k] = 0.f;
    if (half == 0) {              // self term: g[i]*dinv[i]
        uint4 v = g4[i * 16 + li];
        acc_row(acc, v, di);
    }
    int t = s + half;
    for (; t + 6 < e; t += 8) {   // 4 rows in flight per half-warp
        int j0 = g_csr[t], j1 = g_csr[t + 2], j2 = g_csr[t + 4], j3 = g_csr[t + 6];
        float d0 = g_dinv[j0], d1 = g_dinv[j1], d2 = g_dinv[j2], d3 = g_dinv[j3];
        uint4 v0 = g4[j0 * 16 + li];
        uint4 v1 = g4[j1 * 16 + li];
        uint4 v2 = g4[j2 * 16 + li];
        uint4 v3 = g4[j3 * 16 + li];
        acc_row(acc, v0, d0);
        acc_row(acc, v1, d1);
        acc_row(acc, v2, d2);
        acc_row(acc, v3, d3);
    }
    for (; t < e; t += 2) {
        int j = g_csr[t];
        float dj = g_dinv[j];
        uint4 v = g4[j * 16 + li];
        acc_row(acc, v, dj);
    }
#pragma unroll
    for (int k = 0; k < 8; k++)
        acc[k] += __shfl_down_sync(0xffffffffu, acc[k], 16);
    if (half == 0) {
        float4 b0 = *(const float4*)&bias[li * 8];
        float4 b1 = *(const float4*)&bias[li * 8 + 4];
        float r[8];
        r[0] = fmaxf(acc[0] * di + b0.x, 0.f);
        r[1] = fmaxf(acc[1] * di + b0.y, 0.f);
        r[2] = fmaxf(acc[2] * di + b0.z, 0.f);
        r[3] = fmaxf(acc[3] * di + b0.w, 0.f);
        r[4] = fmaxf(acc[4] * di + b1.x, 0.f);
        r[5] = fmaxf(acc[5] * di + b1.y, 0.f);
        r[6] = fmaxf(acc[6] * di + b1.z, 0.f);
        r[7] = fmaxf(acc[7] * di + b1.w, 0.f);
        __half2 h0 = __floats2half2_rn(r[0], r[1]);
        __half2 h1 = __floats2half2_rn(r[2], r[3]);
        __half2 h2 = __floats2half2_rn(r[4], r[5]);
        __half2 h3 = __floats2half2_rn(r[6], r[7]);
        uint4 ov;
        ov.x = *(uint32_t*)&h0; ov.y = *(uint32_t*)&h1;
        ov.z = *(uint32_t*)&h2; ov.w = *(uint32_t*)&h3;
        ((uint4*)out)[i * 16 + li] = ov;
    }
}

// ---------------- pooling: one block per graph, fused divide; reads g_h1 ---------------
__global__ void pool_kernel() {
    __shared__ float s[256];
    const __half* h = g_h1;
    int g = blockIdx.x;
    int tid = threadIdx.x;
    int f = tid & 127, hh = tid >> 7;
    int gs = g_gstart[g], ge = g_gstart[g + 1];
    float acc = 0.f;
    for (int n = gs + hh; n < ge; n += 2)
        acc += __half2float(h[n * F + f]);
    s[tid] = acc;
    __syncthreads();
    if (hh == 0) {
        float cnt = (float)(ge - gs);
        float tot = s[tid] + s[tid + 128];
        g_pool[g * F + f] = tot / fmaxf(cnt, 1.0f);
    }
}

// ---------------- generic small GEMM (fp32): C[M,N] = act(A @ W^T + b) ----------------
__global__ __launch_bounds__(256)
void small_gemm(const float* __restrict__ Aext, int aSel, int aOff, int lda,
                const float* __restrict__ W, const float* __restrict__ bias,
                float* __restrict__ Cext, int cSel, int cOff, int ldc,
                int M, int N, int K, int doRelu) {
    const float* A = (Aext ? Aext : fsel(aSel) + aOff);
    float* C = (Cext ? Cext : fsel(cSel) + cOff);

    __shared__ __align__(16) float As[64][33];
    __shared__ __align__(16) float Ws2[32][68];
    int tid = threadIdx.x;
    int tx = tid & 15, ty = tid >> 4;
    int n0 = blockIdx.x * 64, m0 = blockIdx.y * 64;

    float acc[4][4];
#pragma unroll
    for (int i = 0; i < 4; i++)
#pragma unroll
        for (int j = 0; j < 4; j++) acc[i][j] = 0.f;

    for (int kc = 0; kc < K; kc += 32) {
#pragma unroll
        for (int j = 0; j < 8; j++) {
            int lin = j * 256 + tid;
            int m = lin >> 5, k = lin & 31;
            As[m][k] = (m0 + m < M) ? A[(m0 + m) * lda + kc + k] : 0.f;
        }
#pragma unroll
        for (int j = 0; j < 8; j++) {
            int lin = j * 256 + tid;
            int n = lin >> 5, k = lin & 31;
            Ws2[k][n] = (n0 + n < N) ? W[(n0 + n) * K + kc + k] : 0.f;
        }
        __syncthreads();
#pragma unroll
        for (int k = 0; k < 32; k++) {
            float aa[4];
#pragma unroll
            for (int i = 0; i < 4; i++) aa[i] = As[ty * 4 + i][k];
            float4 b = *(const float4*)&Ws2[k][tx * 4];
            float bb[4] = {b.x, b.y, b.z, b.w};
#pragma unroll
            for (int i = 0; i < 4; i++)
#pragma unroll
                for (int j = 0; j < 4; j++) acc[i][j] += aa[i] * bb[j];
        }
        __syncthreads();
    }
#pragma unroll
    for (int i = 0; i < 4; i++) {
        int m = m0 + ty * 4 + i;
        if (m < M) {
#pragma unroll
            for (int j = 0; j < 4; j++) {
                int n = n0 + tx * 4 + j;
                if (n < N) {
                    float v = acc[i][j];
                    if (bias) v += bias[n];
                    if (doRelu) v = fmaxf(v, 0.f);
                    C[m * ldc + n] = v;
                }
            }
        }
    }
}

// ---------------- launch ----------------
extern "C" void kernel_launch(void* const* d_in, const int* in_sizes, int n_in,
                              void* d_out, int out_size) {
    const float* x         = (const float*)d_in[0];
    const int*   ei        = (const int*)d_in[1];
    const int*   batch     = (const int*)d_in[2];
    const float* mol       = (const float*)d_in[3];
    const float* gcn_W     = (const float*)d_in[4];
    const float* gcn_b     = (const float*)d_in[5];
    const float* gcn_out_W = (const float*)d_in[6];
    const float* gcn_out_b = (const float*)d_in[7];
    const float* mlp_W     = (const float*)d_in[8];
    const float* mlp_b     = (const float*)d_in[9];
    const float* mlp_out_W = (const float*)d_in[10];
    const float* mlp_out_b = (const float*)d_in[11];
    const float* pred_W1   = (const float*)d_in[12];
    const float* pred_b1   = (const float*)d_in[13];
    const float* pred_W2   = (const float*)d_in[14];
    const float* pred_b2   = (const float*)d_in[15];
    const float* out_W     = (const float*)d_in[16];
    const float* out_b     = (const float*)d_in[17];
    float* out = (float*)d_out;

    static cudaStream_t sP = 0, sM = 0;
    static cudaEvent_t evRoot = 0, evP = 0, evM = 0;
    if (!sP) {
        cudaStreamCreateWithFlags(&sP, cudaStreamNonBlocking);
        cudaStreamCreateWithFlags(&sM, cudaStreamNonBlocking);
        cudaEventCreateWithFlags(&evRoot, cudaEventDisableTiming);
        cudaEventCreateWithFlags(&evP, cudaEventDisableTiming);
        cudaEventCreateWithFlags(&evM, cudaEventDisableTiming);
        cudaFuncSetAttribute(gemm_f16, cudaFuncAttributeMaxDynamicSharedMemorySize, GEMM_SMEM);
    }

    const int GB = (N_NODES + 127) / 128;       // 391
    const int AB = (N_NODES * 32 + 255) / 256;  // 6250

    // ---- fork ----
    cudaEventRecord(evRoot, 0);
    cudaStreamWaitEvent(sP, evRoot, 0);
    cudaStreamWaitEvent(sM, evRoot, 0);

    // stream P: graph preprocessing
    init_kernel<<<196, 256, 0, sP>>>();
    degcnt_kernel<<<3125, 256, 0, sP>>>(ei + N_EDGES, batch);
    scanA_kernel<<<NB, 256, 0, sP>>>();
    scanB_kernel<<<1, NB, 0, sP>>>();
    scanC_kernel<<<NB, 256, 0, sP>>>();
    csr_fill_kernel<<<3125, 256, 0, sP>>>(ei, ei + N_EDGES);
    gstart_kernel<<<1, 256, 0, sP>>>();
    cudaEventRecord(evP, sP);

    // stream M: MLP branch -> g_concat[:, 128:192]
    small_gemm<<<dim3(4, 4), 256, 0, sM>>>(mol, -1, 0, 256, mlp_W,         mlp_b,       nullptr, 3, 0, 256, 256, 256, 256, 1);
    small_gemm<<<dim3(4, 4), 256, 0, sM>>>(nullptr, 3, 0, 256, mlp_W + 65536, mlp_b + 256, nullptr, 4, 0, 256, 256, 256, 256, 1);
    small_gemm<<<dim3(1, 4), 256, 0, sM>>>(nullptr, 4, 0, 256, mlp_out_W,  mlp_out_b,   nullptr, 2, 128, 192, 256, 64, 256, 1);
    cudaEventRecord(evM, sM);

    // main stream: g1 = x @ W1^T -> h0 (overlaps preprocessing)
    gemm_f16<<<GB, 256, GEMM_SMEM>>>(x, -1, gcn_W, 0, N_NODES);

    // join preprocessing, then GCN chain (standalone agg kernels at high occupancy)
    cudaStreamWaitEvent(0, evP, 0);
    agg_kernel<<<AB, 256>>>(0, 1, gcn_b);
    gemm_f16<<<GB, 256, GEMM_SMEM>>>(nullptr, 1, gcn_W + 128 * 128, 0, N_NODES);
    agg_kernel<<<AB, 256>>>(0, 1, gcn_b + 128);
    gemm_f16<<<GB, 256, GEMM_SMEM>>>(nullptr, 1, gcn_W + 2 * 128 * 128, 0, N_NODES);
    agg_kernel<<<AB, 256>>>(0, 1, gcn_b + 256);

    // pool(h3) -> g_pool, then commuted final GCN linear -> concat[:,0:128]
    pool_kernel<<<N_GRAPHS, 256>>>();
    small_gemm<<<dim3(2, 4), 256>>>(nullptr, 5, 0, 128, gcn_out_W, gcn_out_b, nullptr, 2, 0, 192, N_GRAPHS, 128, 128, 0);

    // join MLP branch, then prediction head
    cudaStreamWaitEvent(0, evM, 0);
    small_gemm<<<dim3(4, 4), 256>>>(nullptr, 2, 0, 192, pred_W1, pred_b1, nullptr, 3, 0, 256, 256, 256, 192, 1);
    small_gemm<<<dim3(4, 4), 256>>>(nullptr, 3, 0, 256, pred_W2, pred_b2, nullptr, 4, 0, 256, 256, 256, 256, 1);
    small_gemm<<<dim3(1, 4), 256>>>(nullptr, 4, 0, 256, out_W,   out_b,   out,     0, 0, 1,   256, 1,   256, 0);
}

// round 9
// speedup vs baseline: 1.2592x; 1.0187x over previous
#include <cuda_runtime.h>
#include <cuda_fp16.h>
#include <math.h>
#include <stdint.h>

#define N_NODES  50000
#define N_EDGES  800000
#define N_GRAPHS 256
#define F        128
#define NB       256   // scan blocks
#define CH       196   // nodes per scan block (256*196 >= 50000)

// ---------------- scratch (static __device__ — no allocation anywhere) ----------------
__device__ __half g_h0[N_NODES * F];
__device__ __half g_h1[N_NODES * F];
__device__ float  g_dinv[N_NODES];
__device__ int    g_deg[N_NODES];
__device__ int    g_colptr[N_NODES + 1];
__device__ int    g_cursor[N_NODES];
__device__ int    g_csr[N_EDGES];
__device__ int    g_part[NB];
__device__ int    g_counti[N_GRAPHS];
__device__ float  g_concat[N_GRAPHS * 192];
__device__ float  g_s0[N_GRAPHS * 256];
__device__ float  g_s1[N_GRAPHS * 256];

__device__ __forceinline__ __half* hsel(int s) { return s == 0 ? g_h0 : g_h1; }
__device__ __forceinline__ float* fsel(int s) {
    switch (s) { case 2: return g_concat; case 3: return g_s0; default: return g_s1; }
}

// ---------------- init ----------------
__global__ void init_kernel() {
    int i = blockIdx.x * blockDim.x + threadIdx.x;
    if (i < N_NODES)  g_deg[i] = 0;
    if (i < N_GRAPHS) g_counti[i] = 0;
}

// ---------------- degree histogram + per-graph counts (int4 vectorized) ----------------
__global__ void degcnt_kernel(const int* __restrict__ col, const int* __restrict__ batch) {
    int idx = blockIdx.x * blockDim.x + threadIdx.x;
    if (idx < N_EDGES / 4) {
        int4 c = ((const int4*)col)[idx];
        atomicAdd(&g_deg[c.x], 1);
        atomicAdd(&g_deg[c.y], 1);
        atomicAdd(&g_deg[c.z], 1);
        atomicAdd(&g_deg[c.w], 1);
    }
    if (idx < N_NODES / 4) {
        int4 b = ((const int4*)batch)[idx];
        atomicAdd(&g_counti[b.x], 1);
        atomicAdd(&g_counti[b.y], 1);
        atomicAdd(&g_counti[b.z], 1);
        atomicAdd(&g_counti[b.w], 1);
    }
    // tail: 50000 = 4*12500 exact; 800000 = 4*200000 exact
}

// ---------------- scanA: per-block partial sums of degrees ----------------
__global__ void scanA_kernel() {
    __shared__ int s[256];
    int t = threadIdx.x, b = blockIdx.x;
    int i = b * CH + t;
    int v = (t < CH && i < N_NODES) ? g_deg[i] : 0;
    s[t] = v;
    __syncthreads();
    for (int off = 128; off > 0; off >>= 1) {
        if (t < off) s[t] += s[t + off];
        __syncthreads();
    }
    if (t == 0) g_part[b] = s[0];
}

// ---------------- scanC: per-block scan + self-computed partial prefix (+dinv) ----------
__global__ void scanC_kernel() {
    __shared__ int sp[NB];
    __shared__ int s[256];
    int t = threadIdx.x, b = blockIdx.x;
    // scan the 256 partials locally (replaces scanB kernel)
    sp[t] = g_part[t];
    __syncthreads();
    for (int off = 1; off < NB; off <<= 1) {
        int v = (t >= off) ? sp[t - off] : 0;
        __syncthreads();
        sp[t] += v;
        __syncthreads();
    }
    int boff = (b > 0) ? sp[b - 1] : 0;

    int i = b * CH + t;
    int d = (t < CH && i < N_NODES) ? g_deg[i] : 0;
    s[t] = d;
    __syncthreads();
    for (int off = 1; off < 256; off <<= 1) {
        int v = (t >= off) ? s[t - off] : 0;
        __syncthreads();
        s[t] += v;
        __syncthreads();
    }
    if (t < CH && i < N_NODES) {
        int cp = boff + s[t] - d;
        g_colptr[i] = cp;
        g_cursor[i] = cp;
        g_dinv[i]   = rsqrtf((float)d + 1.0f);
    }
    if (b == 0 && t == 0) g_colptr[N_NODES] = N_EDGES;
}

// ---------------- CSR fill (int4 vectorized, 4 edges/thread) ----------------
__global__ void csr_fill_kernel(const int* __restrict__ row,
                                const int* __restrict__ col) {
    int idx = blockIdx.x * blockDim.x + threadIdx.x;
    if (idx < N_EDGES / 4) {
        int4 r = ((const int4*)row)[idx];
        int4 c = ((const int4*)col)[idx];
        int p;
        p = atomicAdd(&g_cursor[c.x], 1); g_csr[p] = r.x;
        p = atomicAdd(&g_cursor[c.y], 1); g_csr[p] = r.y;
        p = atomicAdd(&g_cursor[c.z], 1); g_csr[p] = r.z;
        p = atomicAdd(&g_cursor[c.w], 1); g_csr[p] = r.w;
    }
}

// ---------------- fp16 MMA helper ----------------
__device__ __forceinline__ void mma_f16(float (&c)[4], const uint32_t (&a)[4],
                                        uint32_t b0, uint32_t b1) {
    asm("mma.sync.aligned.m16n8k16.row.col.f32.f16.f16.f32 "
        "{%0,%1,%2,%3},{%4,%5,%6,%7},{%8,%9},{%0,%1,%2,%3};"
        : "+f"(c[0]), "+f"(c[1]), "+f"(c[2]), "+f"(c[3])
        : "r"(a[0]), "r"(a[1]), "r"(a[2]), "r"(a[3]), "r"(b0), "r"(b1));
}

// ---------------- fp16 tensor-core GEMM: C[M,128] = A[M,128] @ W[128,128]^T -------------
#define HS 136
#define GEMM_SMEM (2 * 128 * HS * 2)
__global__ __launch_bounds__(256)
void gemm_f16(const float* __restrict__ Aext, int aSel,
              const float* __restrict__ W, int cSel, int M) {
    extern __shared__ __half sh[];
    __half* As = sh;              // [128][HS]
    __half* Ws = sh + 128 * HS;   // [128][HS]
    __half* C = hsel(cSel);

    int tid = threadIdx.x;
    int wid = tid >> 5, lane = tid & 31;
    int group = lane >> 2, tig = lane & 3;
    int warpM = wid & 3, warpN = wid >> 2;
    int m0 = blockIdx.x * 128;

    if (Aext) {
#pragma unroll
        for (int i = 0; i < 8; i++) {
            int lin = i * 256 + tid;
            int r = lin >> 4, c = (lin & 15) * 8;
            float4 v0 = make_float4(0.f, 0.f, 0.f, 0.f), v1 = v0;
            if (m0 + r < M) {
                v0 = *(const float4*)&Aext[(m0 + r) * 128 + c];
                v1 = *(const float4*)&Aext[(m0 + r) * 128 + c + 4];
            }
            __half2 h0 = __floats2half2_rn(v0.x, v0.y);
            __half2 h1 = __floats2half2_rn(v0.z, v0.w);
            __half2 h2 = __floats2half2_rn(v1.x, v1.y);
            __half2 h3 = __floats2half2_rn(v1.z, v1.w);
            uint4 t;
            t.x = *(uint32_t*)&h0; t.y = *(uint32_t*)&h1;
            t.z = *(uint32_t*)&h2; t.w = *(uint32_t*)&h3;
            *(uint4*)&As[r * HS + c] = t;
        }
    } else {
        const __half* A = hsel(aSel);
#pragma unroll
        for (int i = 0; i < 8; i++) {
            int lin = i * 256 + tid;
            int r = lin >> 4, c = (lin & 15) * 8;
            uint4 t = make_uint4(0, 0, 0, 0);
            if (m0 + r < M) t = *(const uint4*)&A[(m0 + r) * 128 + c];
            *(uint4*)&As[r * HS + c] = t;
        }
    }
#pragma unroll
    for (int i = 0; i < 16; i++) {
        int lin = i * 256 + tid;
        int n = lin >> 5, c = (lin & 31) * 4;
        float4 v = *(const float4*)&W[n * 128 + c];
        __half2 h0 = __floats2half2_rn(v.x, v.y);
        __half2 h1 = __floats2half2_rn(v.z, v.w);
        uint2 t;
        t.x = *(uint32_t*)&h0; t.y = *(uint32_t*)&h1;
        *(uint2*)&Ws[n * HS + c] = t;
    }
    __syncthreads();

    float acc[2][8][4];
#pragma unroll
    for (int mt = 0; mt < 2; mt++)
#pragma unroll
        for (int nt = 0; nt < 8; nt++)
#pragma unroll
            for (int i = 0; i < 4; i++) acc[mt][nt][i] = 0.f;

#pragma unroll
    for (int ks = 0; ks < 8; ks++) {
        int k0 = ks * 16;
        uint32_t a[2][4];
#pragma unroll
        for (int mt = 0; mt < 2; mt++) {
            int r = warpM * 32 + mt * 16 + group;
            a[mt][0] = *(uint32_t*)&As[r * HS + k0 + 2 * tig];
            a[mt][1] = *(uint32_t*)&As[(r + 8) * HS + k0 + 2 * tig];
            a[mt][2] = *(uint32_t*)&As[r * HS + k0 + 8 + 2 * tig];
            a[mt][3] = *(uint32_t*)&As[(r + 8) * HS + k0 + 8 + 2 * tig];
        }
#pragma unroll
        for (int nt = 0; nt < 8; nt++) {
            int n = warpN * 64 + nt * 8 + group;
            uint32_t b0 = *(uint32_t*)&Ws[n * HS + k0 + 2 * tig];
            uint32_t b1 = *(uint32_t*)&Ws[n * HS + k0 + 8 + 2 * tig];
            mma_f16(acc[0][nt], a[0], b0, b1);
            mma_f16(acc[1][nt], a[1], b0, b1);
        }
    }
#pragma unroll
    for (int mt = 0; mt < 2; mt++) {
#pragma unroll
        for (int hh = 0; hh < 2; hh++) {
            int m = m0 + warpM * 32 + mt * 16 + group + hh * 8;
            if (m < M) {
#pragma unroll
                for (int nt = 0; nt < 8; nt++) {
                    int n = warpN * 64 + nt * 8 + tig * 2;
                    __half2 hv = __floats2half2_rn(acc[mt][nt][hh * 2 + 0],
                                                   acc[mt][nt][hh * 2 + 1]);
                    *(uint32_t*)&C[m * 128 + n] = *(uint32_t*)&hv;
                }
            }
        }
    }
}

// ---------------- CSR aggregation (half, uint4, 4 rows in flight per half-warp) ----------
__device__ __forceinline__ void acc_row(float (&a)[8], uint4 v, float sc) {
    float2 p;
    p = __half22float2(*(__half2*)&v.x); a[0] += p.x * sc; a[1] += p.y * sc;
    p = __half22float2(*(__half2*)&v.y); a[2] += p.x * sc; a[3] += p.y * sc;
    p = __half22float2(*(__half2*)&v.z); a[4] += p.x * sc; a[5] += p.y * sc;
    p = __half22float2(*(__half2*)&v.w); a[6] += p.x * sc; a[7] += p.y * sc;
}

__global__ __launch_bounds__(256)
void agg_kernel(int srcSel, int dstSel, const float* __restrict__ bias) {
    const uint4* g4 = (const uint4*)hsel(srcSel);
    __half* out = hsel(dstSel);
    int warp = (blockIdx.x * blockDim.x + threadIdx.x) >> 5;
    int lane = threadIdx.x & 31;
    if (warp >= N_NODES) return;
    int i = warp;
    int half = lane >> 4, li = lane & 15;
    int s = g_colptr[i], e = g_colptr[i + 1];

    float di = g_dinv[i];
    float acc[8];
#pragma unroll
    for (int k = 0; k < 8; k++) acc[k] = 0.f;
    if (half == 0) {
        uint4 v = g4[i * 16 + li];
        acc_row(acc, v, di);
    }
    int t = s + half;
    for (; t + 6 < e; t += 8) {
        int j0 = g_csr[t], j1 = g_csr[t + 2], j2 = g_csr[t + 4], j3 = g_csr[t + 6];
        float d0 = g_dinv[j0], d1 = g_dinv[j1], d2 = g_dinv[j2], d3 = g_dinv[j3];
        uint4 v0 = g4[j0 * 16 + li];
        uint4 v1 = g4[j1 * 16 + li];
        uint4 v2 = g4[j2 * 16 + li];
        uint4 v3 = g4[j3 * 16 + li];
        acc_row(acc, v0, d0);
        acc_row(acc, v1, d1);
        acc_row(acc, v2, d2);
        acc_row(acc, v3, d3);
    }
    for (; t < e; t += 2) {
        int j = g_csr[t];
        float dj = g_dinv[j];
        uint4 v = g4[j * 16 + li];
        acc_row(acc, v, dj);
    }
#pragma unroll
    for (int k = 0; k < 8; k++)
        acc[k] += __shfl_down_sync(0xffffffffu, acc[k], 16);
    if (half == 0) {
        float4 b0 = *(const float4*)&bias[li * 8];
        float4 b1 = *(const float4*)&bias[li * 8 + 4];
        float r[8];
        r[0] = fmaxf(acc[0] * di + b0.x, 0.f);
        r[1] = fmaxf(acc[1] * di + b0.y, 0.f);
        r[2] = fmaxf(acc[2] * di + b0.z, 0.f);
        r[3] = fmaxf(acc[3] * di + b0.w, 0.f);
        r[4] = fmaxf(acc[4] * di + b1.x, 0.f);
        r[5] = fmaxf(acc[5] * di + b1.y, 0.f);
        r[6] = fmaxf(acc[6] * di + b1.z, 0.f);
        r[7] = fmaxf(acc[7] * di + b1.w, 0.f);
        __half2 h0 = __floats2half2_rn(r[0], r[1]);
        __half2 h1 = __floats2half2_rn(r[2], r[3]);
        __half2 h2 = __floats2half2_rn(r[4], r[5]);
        __half2 h3 = __floats2half2_rn(r[6], r[7]);
        uint4 ov;
        ov.x = *(uint32_t*)&h0; ov.y = *(uint32_t*)&h1;
        ov.z = *(uint32_t*)&h2; ov.w = *(uint32_t*)&h3;
        ((uint4*)out)[i * 16 + li] = ov;
    }
}

// ---------------- pool + commuted gcn_out linear, with in-block graph ranges ------------
// block g: pooled = mean(h1 rows of graph g); concat[g,0:128] = Wout @ pooled + bout
__global__ __launch_bounds__(256)
void pool_kernel(const float* __restrict__ Wout, const float* __restrict__ bout) {
    __shared__ int sc[N_GRAPHS];
    __shared__ __align__(16) float pool[128];
    __shared__ float part[256];
    int g = blockIdx.x, t = threadIdx.x;

    // in-block prefix of counts (replaces gstart kernel)
    int cnt_g = g_counti[g];
    sc[t] = g_counti[t];
    __syncthreads();
    for (int off = 1; off < N_GRAPHS; off <<= 1) {
        int v = (t >= off) ? sc[t - off] : 0;
        __syncthreads();
        sc[t] += v;
        __syncthreads();
    }
    int ge = sc[g], gs = ge - cnt_g;

    int f = t & 127, hh = t >> 7;
    float acc = 0.f;
    for (int n = gs + hh; n < ge; n += 2)
        acc += __half2float(g_h1[n * F + f]);
    part[t] = acc;
    __syncthreads();
    if (hh == 0)
        pool[f] = (part[f] + part[f + 128]) / fmaxf((float)cnt_g, 1.0f);
    __syncthreads();

    // matvec: output f, k-half hh (64 each)
    float sum = 0.f;
    const float4* w4 = (const float4*)&Wout[f * 128 + hh * 64];
    const float4* p4 = (const float4*)&pool[hh * 64];
#pragma unroll
    for (int j = 0; j < 16; j++) {
        float4 w = w4[j], p = p4[j];
        sum += w.x * p.x + w.y * p.y + w.z * p.z + w.w * p.w;
    }
    part[t] = sum;
    __syncthreads();
    if (hh == 0)
        g_concat[g * 192 + f] = part[f] + part[f + 128] + bout[f];
}

// ---------------- generic small GEMM (fp32): C[M,N] = act(A @ W^T + b) ----------------
__global__ __launch_bounds__(256)
void small_gemm(const float* __restrict__ Aext, int aSel, int aOff, int lda,
                const float* __restrict__ W, const float* __restrict__ bias,
                float* __restrict__ Cext, int cSel, int cOff, int ldc,
                int M, int N, int K, int doRelu) {
    const float* A = (Aext ? Aext : fsel(aSel) + aOff);
    float* C = (Cext ? Cext : fsel(cSel) + cOff);

    __shared__ __align__(16) float As[64][33];
    __shared__ __align__(16) float Ws2[32][68];
    int tid = threadIdx.x;
    int tx = tid & 15, ty = tid >> 4;
    int n0 = blockIdx.x * 64, m0 = blockIdx.y * 64;

    float acc[4][4];
#pragma unroll
    for (int i = 0; i < 4; i++)
#pragma unroll
        for (int j = 0; j < 4; j++) acc[i][j] = 0.f;

    for (int kc = 0; kc < K; kc += 32) {
#pragma unroll
        for (int j = 0; j < 8; j++) {
            int lin = j * 256 + tid;
            int m = lin >> 5, k = lin & 31;
            As[m][k] = (m0 + m < M) ? A[(m0 + m) * lda + kc + k] : 0.f;
        }
#pragma unroll
        for (int j = 0; j < 8; j++) {
            int lin = j * 256 + tid;
            int n = lin >> 5, k = lin & 31;
            Ws2[k][n] = (n0 + n < N) ? W[(n0 + n) * K + kc + k] : 0.f;
        }
        __syncthreads();
#pragma unroll
        for (int k = 0; k < 32; k++) {
            float aa[4];
#pragma unroll
            for (int i = 0; i < 4; i++) aa[i] = As[ty * 4 + i][k];
            float4 b = *(const float4*)&Ws2[k][tx * 4];
            float bb[4] = {b.x, b.y, b.z, b.w};
#pragma unroll
            for (int i = 0; i < 4; i++)
#pragma unroll
                for (int j = 0; j < 4; j++) acc[i][j] += aa[i] * bb[j];
        }
        __syncthreads();
    }
#pragma unroll
    for (int i = 0; i < 4; i++) {
        int m = m0 + ty * 4 + i;
        if (m < M) {
#pragma unroll
            for (int j = 0; j < 4; j++) {
                int n = n0 + tx * 4 + j;
                if (n < N) {
                    float v = acc[i][j];
                    if (bias) v += bias[n];
                    if (doRelu) v = fmaxf(v, 0.f);
                    C[m * ldc + n] = v;
                }
            }
        }
    }
}

// ---------------- launch ----------------
extern "C" void kernel_launch(void* const* d_in, const int* in_sizes, int n_in,
                              void* d_out, int out_size) {
    const float* x         = (const float*)d_in[0];
    const int*   ei        = (const int*)d_in[1];
    const int*   batch     = (const int*)d_in[2];
    const float* mol       = (const float*)d_in[3];
    const float* gcn_W     = (const float*)d_in[4];
    const float* gcn_b     = (const float*)d_in[5];
    const float* gcn_out_W = (const float*)d_in[6];
    const float* gcn_out_b = (const float*)d_in[7];
    const float* mlp_W     = (const float*)d_in[8];
    const float* mlp_b     = (const float*)d_in[9];
    const float* mlp_out_W = (const float*)d_in[10];
    const float* mlp_out_b = (const float*)d_in[11];
    const float* pred_W1   = (const float*)d_in[12];
    const float* pred_b1   = (const float*)d_in[13];
    const float* pred_W2   = (const float*)d_in[14];
    const float* pred_b2   = (const float*)d_in[15];
    const float* out_W     = (const float*)d_in[16];
    const float* out_b     = (const float*)d_in[17];
    float* out = (float*)d_out;

    static cudaStream_t sP = 0, sM = 0;
    static cudaEvent_t evRoot = 0, evP = 0, evM = 0;
    if (!sP) {
        cudaStreamCreateWithFlags(&sP, cudaStreamNonBlocking);
        cudaStreamCreateWithFlags(&sM, cudaStreamNonBlocking);
        cudaEventCreateWithFlags(&evRoot, cudaEventDisableTiming);
        cudaEventCreateWithFlags(&evP, cudaEventDisableTiming);
        cudaEventCreateWithFlags(&evM, cudaEventDisableTiming);
        cudaFuncSetAttribute(gemm_f16, cudaFuncAttributeMaxDynamicSharedMemorySize, GEMM_SMEM);
    }

    const int GB = (N_NODES + 127) / 128;       // 391
    const int AB = (N_NODES * 32 + 255) / 256;  // 6250
    const int EB = (N_EDGES / 4 + 255) / 256;   // 782

    // ---- fork ----
    cudaEventRecord(evRoot, 0);
    cudaStreamWaitEvent(sP, evRoot, 0);
    cudaStreamWaitEvent(sM, evRoot, 0);

    // stream P: graph preprocessing (5 kernels; evP right after csr_fill)
    init_kernel<<<196, 256, 0, sP>>>();
    degcnt_kernel<<<EB, 256, 0, sP>>>(ei + N_EDGES, batch);
    scanA_kernel<<<NB, 256, 0, sP>>>();
    scanC_kernel<<<NB, 256, 0, sP>>>();
    csr_fill_kernel<<<EB, 256, 0, sP>>>(ei, ei + N_EDGES);
    cudaEventRecord(evP, sP);

    // stream M: MLP branch -> g_concat[:, 128:192]
    small_gemm<<<dim3(4, 4), 256, 0, sM>>>(mol, -1, 0, 256, mlp_W,         mlp_b,       nullptr, 3, 0, 256, 256, 256, 256, 1);
    small_gemm<<<dim3(4, 4), 256, 0, sM>>>(nullptr, 3, 0, 256, mlp_W + 65536, mlp_b + 256, nullptr, 4, 0, 256, 256, 256, 256, 1);
    small_gemm<<<dim3(1, 4), 256, 0, sM>>>(nullptr, 4, 0, 256, mlp_out_W,  mlp_out_b,   nullptr, 2, 128, 192, 256, 64, 256, 1);
    cudaEventRecord(evM, sM);

    // main stream: g1 = x @ W1^T -> h0 (overlaps preprocessing)
    gemm_f16<<<GB, 256, GEMM_SMEM>>>(x, -1, gcn_W, 0, N_NODES);

    // join preprocessing, then GCN chain
    cudaStreamWaitEvent(0, evP, 0);
    agg_kernel<<<AB, 256>>>(0, 1, gcn_b);
    gemm_f16<<<GB, 256, GEMM_SMEM>>>(nullptr, 1, gcn_W + 128 * 128, 0, N_NODES);
    agg_kernel<<<AB, 256>>>(0, 1, gcn_b + 128);
    gemm_f16<<<GB, 256, GEMM_SMEM>>>(nullptr, 1, gcn_W + 2 * 128 * 128, 0, N_NODES);
    agg_kernel<<<AB, 256>>>(0, 1, gcn_b + 256);

    // pool + commuted gcn_out linear -> concat[:,0:128]
    pool_kernel<<<N_GRAPHS, 256>>>(gcn_out_W, gcn_out_b);

    // join MLP branch, then prediction head
    cudaStreamWaitEvent(0, evM, 0);
    small_gemm<<<dim3(4, 4), 256>>>(nullptr, 2, 0, 192, pred_W1, pred_b1, nullptr, 3, 0, 256, 256, 256, 192, 1);
    small_gemm<<<dim3(4, 4), 256>>>(nullptr, 3, 0, 256, pred_W2, pred_b2, nullptr, 4, 0, 256, 256, 256, 256, 1);
    small_gemm<<<dim3(1, 4), 256>>>(nullptr, 4, 0, 256, out_W,   out_b,   out,     0, 0, 1,   256, 1,   256, 0);
}